// round 3
// baseline (speedup 1.0000x reference)
#include <cuda_runtime.h>
#include <math.h>

#define NB 4
#define NN 4096
#define NK 32
#define NF 128
#define EPSF 1e-8f

// g_acc layout
#define OFF_DFLAT 0        // [B][N]
#define OFF_NUM   16384    // [B]
#define OFF_SS    16388    // [K][K]
#define OFF_PEMB  17412    // [B][K][F]
#define OFF_CSUM  33796    // [B][F]
#define OFF_RAW   34308    // [B][K][K]
#define OFF_AS2   38404    // [B][K]
#define ACC_TOTAL 38532

// output layout (tuple flattened)
#define OUT_EMB   0
#define OUT_ADJ   16384
#define OUT_S     20480
#define OUT_MLOSS 544768
#define OUT_OLOSS 544769

__device__ float g_s_soft[NN * NK];
__device__ float g_w[NN];
__device__ int   g_cluster[NB * NN];
__device__ float g_acc[ACC_TOTAL];
__device__ float g_Rs[8u * NB * NN * NK];   // per-m-slice bucket sums, 16MB

__global__ void k_zero() {
    for (int i = blockIdx.x * blockDim.x + threadIdx.x; i < ACC_TOTAL;
         i += gridDim.x * blockDim.x)
        g_acc[i] = 0.0f;
}

// softmax(logits/t2) -> g_s_soft, w[n]=sum sq; per-batch argmax -> g_cluster; s_sample -> out
__global__ void k_soft(const float* __restrict__ logits,
                       const float* __restrict__ gumbel,
                       float* __restrict__ out) {
    int n = blockIdx.x * 128 + threadIdx.x;
    float lg[32];
    const float4* lp = (const float4*)(logits + n * NK);
#pragma unroll
    for (int i = 0; i < 8; i++) {
        float4 v = lp[i];
        lg[4*i] = v.x; lg[4*i+1] = v.y; lg[4*i+2] = v.z; lg[4*i+3] = v.w;
    }
    const float t1 = 0.99995f;
    const float t2 = 0.99995f * 0.99995f;

    float x[32], mx = -3.4e38f;
#pragma unroll
    for (int k = 0; k < 32; k++) { x[k] = lg[k] / t2; mx = fmaxf(mx, x[k]); }
    float s = 0.0f;
#pragma unroll
    for (int k = 0; k < 32; k++) { x[k] = expf(x[k] - mx); s += x[k]; }
    float inv = 1.0f / s, w = 0.0f;
#pragma unroll
    for (int k = 0; k < 32; k++) { x[k] *= inv; w += x[k] * x[k]; }
    float4* sp = (float4*)(g_s_soft + n * NK);
#pragma unroll
    for (int i = 0; i < 8; i++)
        sp[i] = make_float4(x[4*i], x[4*i+1], x[4*i+2], x[4*i+3]);
    g_w[n] = w;

#pragma unroll
    for (int b = 0; b < NB; b++) {
        const float4* gp = (const float4*)(gumbel + ((size_t)(b * NN + n)) * NK);
        float best = -3.4e38f; int bi = 0;
#pragma unroll
        for (int i = 0; i < 8; i++) {
            float4 g = gp[i];
            float z;
            z = lg[4*i+0] / t1 + g.x; if (z > best) { best = z; bi = 4*i+0; }
            z = lg[4*i+1] / t1 + g.y; if (z > best) { best = z; bi = 4*i+1; }
            z = lg[4*i+2] / t1 + g.z; if (z > best) { best = z; bi = 4*i+2; }
            z = lg[4*i+3] / t1 + g.w; if (z > best) { best = z; bi = 4*i+3; }
        }
        g_cluster[b * NN + n] = bi;
        float4* op = (float4*)(out + OUT_S + ((size_t)(b * NN + n)) * NK);
#pragma unroll
        for (int i = 0; i < 8; i++) {
            float4 o;
            o.x = (4*i+0 == bi) ? 1.0f + EPSF : EPSF;
            o.y = (4*i+1 == bi) ? 1.0f + EPSF : EPSF;
            o.z = (4*i+2 == bi) ? 1.0f + EPSF : EPSF;
            o.w = (4*i+3 == bi) ? 1.0f + EPSF : EPSF;
            op[i] = o;
        }
    }
}

// ss = s_soft^T s_soft
__global__ void k_ss() {
    __shared__ float tile[32 * 32];
    int tid = threadIdx.x;
    float acc[4] = {0, 0, 0, 0};
    int base_n = blockIdx.x * 128;
    for (int ch = 0; ch < 4; ch++) {
        __syncthreads();
        const float4* src = (const float4*)(g_s_soft + (base_n + ch * 32) * NK);
        ((float4*)tile)[tid] = src[tid];
        __syncthreads();
#pragma unroll 4
        for (int r = 0; r < 32; r++) {
#pragma unroll
            for (int p = 0; p < 4; p++) {
                int pr = tid + p * 256;
                acc[p] += tile[r * 32 + (pr >> 5)] * tile[r * 32 + (pr & 31)];
            }
        }
    }
#pragma unroll
    for (int p = 0; p < 4; p++)
        atomicAdd(&g_acc[OFF_SS + tid + p * 256], acc[p]);
}

// main adj pass: grid 512 = 64 n-tiles x 8 m-slices, 64 thr, thread = one n-row
__global__ void __launch_bounds__(64) k_main(const float* __restrict__ adj) {
    __shared__ float s_m[32 * 32];
    __shared__ int   c_s[4 * 32];
    __shared__ float R_priv[4 * 64 * 33];
    int tid = threadIdx.x;
    int nt = blockIdx.x >> 3, ms = blockIdx.x & 7;
    int n = nt * 64 + tid;
    int mbase = ms * 512;

    for (int i = tid; i < 4 * 64 * 33; i += 64) R_priv[i] = 0.0f;

    float s_n[32];
    const float4* sp = (const float4*)(g_s_soft + n * NK);
#pragma unroll
    for (int i = 0; i < 8; i++) {
        float4 v = sp[i];
        s_n[4*i] = v.x; s_n[4*i+1] = v.y; s_n[4*i+2] = v.z; s_n[4*i+3] = v.w;
    }
    float mc[4] = {0, 0, 0, 0}, rs[4] = {0, 0, 0, 0};

    for (int ch = 0; ch < 16; ch++) {
        int m0 = mbase + ch * 32;
        __syncthreads();
        {
            const float4* src = (const float4*)(g_s_soft + m0 * NK);
            float4* dst = (float4*)s_m;
#pragma unroll
            for (int i = 0; i < 4; i++) dst[tid + i * 64] = src[tid + i * 64];
        }
        for (int i = tid; i < 128; i += 64)
            c_s[i] = g_cluster[(i >> 5) * NN + m0 + (i & 31)];
        __syncthreads();

        float G[32];
#pragma unroll 4
        for (int j = 0; j < 32; j++) {
            const float4* q = (const float4*)(s_m + j * 32);
            float a = 0.0f;
#pragma unroll
            for (int i = 0; i < 8; i++) {
                float4 v = q[i];
                a += s_n[4*i] * v.x + s_n[4*i+1] * v.y
                   + s_n[4*i+2] * v.z + s_n[4*i+3] * v.w;
            }
            G[j] = a;
        }

#pragma unroll
        for (int b = 0; b < 4; b++) {
            const float4* arow =
                (const float4*)(adj + ((size_t)(b * NN + n)) * NN + m0);
            float* Rp = R_priv + (b * 64 + tid) * 33;
            const int* cp = c_s + b * 32;
            float mcl = 0.0f, rsl = 0.0f;
#pragma unroll
            for (int j4 = 0; j4 < 8; j4++) {
                float4 a = arow[j4];
                int c0 = cp[4*j4], c1 = cp[4*j4+1], c2 = cp[4*j4+2], c3 = cp[4*j4+3];
                mcl += a.x * G[4*j4]   + a.y * G[4*j4+1]
                     + a.z * G[4*j4+2] + a.w * G[4*j4+3];
                rsl += a.x + a.y + a.z + a.w;
                Rp[c0] += a.x; Rp[c1] += a.y; Rp[c2] += a.z; Rp[c3] += a.w;
            }
            mc[b] += mcl; rs[b] += rsl;
        }
    }

#pragma unroll
    for (int b = 0; b < 4; b++) {
        atomicAdd(&g_acc[OFF_DFLAT + b * NN + n], rs[b]);
        float v = mc[b];
#pragma unroll
        for (int o = 16; o > 0; o >>= 1) v += __shfl_down_sync(0xffffffffu, v, o);
        if ((tid & 31) == 0) atomicAdd(&g_acc[OFF_NUM + b], v);
    }
#pragma unroll
    for (int b = 0; b < 4; b++) {
        float* Rp = R_priv + (b * 64 + tid) * 33;
        float4* dst = (float4*)(g_Rs + ((size_t)((ms * 4 + b) * NN + n)) * 32);
#pragma unroll
        for (int i = 0; i < 8; i++)
            dst[i] = make_float4(Rp[4*i], Rp[4*i+1], Rp[4*i+2], Rp[4*i+3]);
    }
}

// emb pooling: grid 64 = B x 16 chunks of 256 rows; 128 threads (one per f)
__global__ void k_emb(const float* __restrict__ emb) {
    __shared__ float acc[32 * 128];
    __shared__ int cl[256];
    int f = threadIdx.x;
    int b = blockIdx.x >> 4, ch = blockIdx.x & 15;
#pragma unroll
    for (int k = 0; k < 32; k++) acc[k * 128 + f] = 0.0f;
    for (int i = f; i < 256; i += 128) cl[i] = g_cluster[b * NN + ch * 256 + i];
    __syncthreads();
    float cs = 0.0f;
    int nbase = ch * 256;
    for (int r = 0; r < 256; r++) {
        float v = emb[((size_t)(b * NN + nbase + r)) * NF + f];
        cs += v;
        acc[cl[r] * 128 + f] += v;
    }
    __syncthreads();
#pragma unroll
    for (int k = 0; k < 32; k++)
        atomicAdd(&g_acc[OFF_PEMB + (b * 32 + k) * 128 + f], acc[k * 128 + f]);
    atomicAdd(&g_acc[OFF_CSUM + b * 128 + f], cs);
}

// pool As2 by row cluster: grid 32 = B x 8 chunks of 512 rows; 256 thr = 8 warps
__global__ void k_oadj() {
    __shared__ float acc[8 * 32 * 32];
    __shared__ float s2[8 * 32];
    int tid = threadIdx.x, w = tid >> 5, l = tid & 31;
    int b = blockIdx.x >> 3, ch = blockIdx.x & 7;
    for (int i = tid; i < 8 * 32 * 32; i += 256) acc[i] = 0.0f;
    __syncthreads();
    float s2l = 0.0f;
    for (int r = w; r < 512; r += 8) {
        int n = ch * 512 + r;
        float as2 = EPSF * g_acc[OFF_DFLAT + b * NN + n];
#pragma unroll
        for (int s = 0; s < 8; s++)
            as2 += g_Rs[((size_t)((s * 4 + b) * NN + n)) * 32 + l];
        int c = g_cluster[b * NN + n];
        acc[(w * 32 + c) * 32 + l] += as2;
        s2l += as2;
    }
    s2[w * 32 + l] = s2l;
    __syncthreads();
#pragma unroll
    for (int p = 0; p < 4; p++) {
        int pr = tid + p * 256;
        float s = 0.0f;
#pragma unroll
        for (int ww = 0; ww < 8; ww++) s += acc[ww * 1024 + pr];
        atomicAdd(&g_acc[OFF_RAW + b * 1024 + pr], s);
    }
    if (tid < 32) {
        float s = 0.0f;
#pragma unroll
        for (int ww = 0; ww < 8; ww++) s += s2[ww * 32 + tid];
        atomicAdd(&g_acc[OFF_AS2 + b * 32 + tid], s);
    }
}

__global__ void k_fin(float* __restrict__ out) {
    __shared__ float red[256];
    __shared__ float adjb[4096];
    __shared__ float dbk[128];
    __shared__ float fro_s;
    int tid = threadIdx.x;

    // mincut loss
    float den[4] = {0, 0, 0, 0};
    for (int i = tid; i < NN; i += 256) {
        float wv = g_w[i];
#pragma unroll
        for (int b = 0; b < 4; b++) den[b] += g_acc[OFF_DFLAT + b * NN + i] * wv;
    }
    float loss = 0.0f;
    for (int b = 0; b < 4; b++) {
        red[tid] = den[b]; __syncthreads();
        for (int s = 128; s > 0; s >>= 1) {
            if (tid < s) red[tid] += red[tid + s];
            __syncthreads();
        }
        if (tid == 0) loss += g_acc[OFF_NUM + b] / red[0];
        __syncthreads();
    }
    if (tid == 0) out[OUT_MLOSS] = -0.25f * loss;

    // ortho loss
    float f2 = 0.0f;
    for (int i = tid; i < 1024; i += 256) {
        float v = g_acc[OFF_SS + i]; f2 += v * v;
    }
    red[tid] = f2; __syncthreads();
    for (int s = 128; s > 0; s >>= 1) {
        if (tid < s) red[tid] += red[tid + s];
        __syncthreads();
    }
    if (tid == 0) fro_s = sqrtf(red[0]);
    __syncthreads();
    float invf = 1.0f / fro_s;
    const float isq = 0.17677669529663687f;  // 1/sqrt(32)
    float o2 = 0.0f;
    for (int i = tid; i < 1024; i += 256) {
        float v = g_acc[OFF_SS + i] * invf;
        if ((i >> 5) == (i & 31)) v -= isq;
        o2 += v * v;
    }
    red[tid] = o2; __syncthreads();
    for (int s = 128; s > 0; s >>= 1) {
        if (tid < s) red[tid] += red[tid + s];
        __syncthreads();
    }
    if (tid == 0) out[OUT_OLOSS] = sqrtf(red[0]);

    // out_emb
    for (int i = tid; i < 16384; i += 256) {
        int b = i >> 12, f = i & 127;
        out[OUT_EMB + i] = g_acc[OFF_PEMB + i] + EPSF * g_acc[OFF_CSUM + b * 128 + f];
    }

    // out_adj
    for (int i = tid; i < 4096; i += 256) {
        int b = i >> 10, k = (i >> 5) & 31, l = i & 31;
        float v = (k == l) ? 0.0f
                 : g_acc[OFF_RAW + i] + EPSF * g_acc[OFF_AS2 + b * 32 + l];
        adjb[i] = v;
    }
    __syncthreads();
    if (tid < 128) {
        float s = 0.0f;
#pragma unroll
        for (int l = 0; l < 32; l++) s += adjb[tid * 32 + l];
        dbk[tid] = sqrtf(s) + EPSF;
    }
    __syncthreads();
    for (int i = tid; i < 4096; i += 256) {
        int b = i >> 10, k = (i >> 5) & 31, l = i & 31;
        out[OUT_ADJ + i] = adjb[i] / (dbk[b * 32 + k] * dbk[b * 32 + l]);
    }
}

extern "C" void kernel_launch(void* const* d_in, const int* in_sizes, int n_in,
                              void* d_out, int out_size) {
    const float* emb    = (const float*)d_in[0];
    const float* adj    = (const float*)d_in[1];
    const float* logits = (const float*)d_in[2];
    const float* gumbel = (const float*)d_in[3];
    float* out = (float*)d_out;
    k_zero<<<40, 1024>>>();
    k_soft<<<32, 128>>>(logits, gumbel, out);
    k_ss<<<32, 256>>>();
    k_main<<<512, 64>>>(adj);
    k_emb<<<64, 128>>>(emb);
    k_oadj<<<32, 256>>>();
    k_fin<<<1, 256>>>(out);
}